// round 1
// baseline (speedup 1.0000x reference)
#include <cuda_runtime.h>
#include <math.h>

#define B_ 8
#define N_ 4096
#define M_ 96
#define NPAD 128
#define OUTW 384          // 3 * N_ANGULAR
#define RCUT 6.0f

__global__ __launch_bounds__(NPAD, 8)
void deepmd_angular_kernel(const float* __restrict__ pos,
                           const float* __restrict__ cell,
                           const float* __restrict__ offs,
                           const float* __restrict__ mask,
                           const int*   __restrict__ neigh,
                           float* __restrict__ out) {
    const int row = blockIdx.x;        // b * N_ + n
    const int b   = row >> 12;         // N_ = 4096
    const int tid = threadIdx.x;

    __shared__ unsigned long long keys[NPAD];
    __shared__ float cv[M_][3];

    // cell row (uniform per block, L1 broadcast)
    const float* cb = cell + b * 9;
    const float c00 = cb[0], c01 = cb[1], c02 = cb[2];
    const float c10 = cb[3], c11 = cb[4], c12 = cb[5];
    const float c20 = cb[6], c21 = cb[7], c22 = cb[8];

    const float* pi = pos + (long)row * 3;
    const float pix = pi[0], piy = pi[1], piz = pi[2];

    if (tid < M_) {
        const long base = (long)row * M_ + tid;
        const int  j    = neigh[base];
        const float ox  = offs[base * 3 + 0];
        const float oy  = offs[base * 3 + 1];
        const float oz  = offs[base * 3 + 2];
        const float msk = mask[base];

        const float* pj = pos + ((long)b * N_ + j) * 3;
        float dx = pj[0] - pix + ox * c00 + oy * c10 + oz * c20;
        float dy = pj[1] - piy + ox * c01 + oy * c11 + oz * c21;
        float dz = pj[2] - piz + ox * c02 + oy * c12 + oz * c22;

        const float d2 = fmaf(dx, dx, fmaf(dy, dy, fmaf(dz, dz, 1e-12f)));
        const float d  = sqrtf(d2);

        float cut = 0.0f;
        if (msk != 0.0f && d < RCUT) {
            // 0.5*(cos(pi*d/rc)+1)/d
            cut = 0.5f * (cospif(d * (1.0f / RCUT)) + 1.0f) / d;
        }

        cv[tid][0] = cut * dx;
        cv[tid][1] = cut * dy;
        cv[tid][2] = cut * dz;

        // key: (cut bits | tie-break). cut >= 0 so the IEEE bit pattern is
        // order-preserving. Low field 127-m: at equal cut, lower original m
        // sorts FIRST in descending order (matches stable argsort(-cut)).
        const unsigned int kb = __float_as_uint(cut);
        keys[tid] = ((unsigned long long)kb << 32) | (unsigned int)(127 - tid);
    } else {
        // pad slots: cut bits 0, low field 0..31 -> strictly smaller than any
        // real entry, so they occupy sorted positions 96..127.
        keys[tid] = (unsigned long long)(127 - tid);
    }
    __syncthreads();

    // Bitonic sort, descending, 128 elements, 1 per thread.
    #pragma unroll
    for (int k = 2; k <= NPAD; k <<= 1) {
        #pragma unroll
        for (int j = k >> 1; j > 0; j >>= 1) {
            const int ixj = tid ^ j;
            if (ixj > tid) {
                const unsigned long long a  = keys[tid];
                const unsigned long long bb = keys[ixj];
                const bool up = ((tid & k) == 0);
                const bool sw = up ? (a < bb) : (a > bb);
                if (sw) { keys[tid] = bb; keys[ixj] = a; }
            }
            __syncthreads();
        }
    }

    float* orow = out + (long)row * OUTW;
    if (tid < M_) {
        const int om = 127 - (int)(keys[tid] & 0xffu);   // original m, 0..95
        orow[tid * 3 + 0] = cv[om][0];
        orow[tid * 3 + 1] = cv[om][1];
        orow[tid * 3 + 2] = cv[om][2];
    } else {
        const int r = M_ * 3 + (tid - M_) * 3;           // 288..383
        orow[r + 0] = 0.0f;
        orow[r + 1] = 0.0f;
        orow[r + 2] = 0.0f;
    }
}

extern "C" void kernel_launch(void* const* d_in, const int* in_sizes, int n_in,
                              void* d_out, int out_size) {
    const float* positions = (const float*)d_in[0];
    const float* cell      = (const float*)d_in[1];
    const float* offsets   = (const float*)d_in[2];
    const float* mask      = (const float*)d_in[3];
    const int*   neighbors = (const int*)d_in[4];
    float* out = (float*)d_out;

    deepmd_angular_kernel<<<B_ * N_, NPAD>>>(positions, cell, offsets, mask,
                                             neighbors, out);
}

// round 2
// speedup vs baseline: 1.5473x; 1.5473x over previous
#include <cuda_runtime.h>
#include <math.h>

#define B_ 8
#define N_ 4096
#define M_ 96
#define OUTW 384          // 3 * N_ANGULAR
#define RCUT 6.0f
#define WARPS 4

__global__ __launch_bounds__(128)
void deepmd_angular_kernel(const float* __restrict__ pos,
                           const float* __restrict__ cell,
                           const float* __restrict__ offs,
                           const float* __restrict__ mask,
                           const int*   __restrict__ neigh,
                           float* __restrict__ out) {
    const int warp = threadIdx.x >> 5;
    const int lane = threadIdx.x & 31;
    const int row  = blockIdx.x * WARPS + warp;   // b*N_ + n
    const int b    = row >> 12;                   // N_ = 4096

    __shared__ float cv[WARPS][M_ * 3];

    const float* cb = cell + b * 9;
    const float c00 = cb[0], c01 = cb[1], c02 = cb[2];
    const float c10 = cb[3], c11 = cb[4], c12 = cb[5];
    const float c20 = cb[6], c21 = cb[7], c22 = cb[8];

    const float* pi = pos + (long)row * 3;
    const float pix = pi[0], piy = pi[1], piz = pi[2];

    unsigned long long key[4];

    if (lane < 24) {
        // this lane owns neighbors m = lane*4 .. lane*4+3 (blocked mapping)
        const long base = (long)row * M_ + lane * 4;
        const int4   jj = *reinterpret_cast<const int4*>(neigh + base);
        const float4 mm = *reinterpret_cast<const float4*>(mask + base);
        const float4* op = reinterpret_cast<const float4*>(offs + base * 3);
        const float4 oA = op[0], oB = op[1], oC = op[2];

        const float ox[4] = {oA.x, oA.w, oB.z, oC.y};
        const float oy[4] = {oA.y, oB.x, oB.w, oC.z};
        const float oz[4] = {oA.z, oB.y, oC.x, oC.w};
        const int   j4[4] = {jj.x, jj.y, jj.z, jj.w};
        const float m4[4] = {mm.x, mm.y, mm.z, mm.w};

        #pragma unroll
        for (int r = 0; r < 4; r++) {
            const float* pj = pos + ((long)b * N_ + j4[r]) * 3;
            const float dx = pj[0] - pix + ox[r] * c00 + oy[r] * c10 + oz[r] * c20;
            const float dy = pj[1] - piy + ox[r] * c01 + oy[r] * c11 + oz[r] * c21;
            const float dz = pj[2] - piz + ox[r] * c02 + oy[r] * c12 + oz[r] * c22;

            const float d = sqrtf(fmaf(dx, dx, fmaf(dy, dy, fmaf(dz, dz, 1e-12f))));

            float cut = 0.0f;
            if (m4[r] != 0.0f && d < RCUT)
                cut = 0.5f * (cospif(d * (1.0f / RCUT)) + 1.0f) / d;

            const int m = lane * 4 + r;
            cv[warp][m * 3 + 0] = cut * dx;
            cv[warp][m * 3 + 1] = cut * dy;
            cv[warp][m * 3 + 2] = cut * dz;

            // key: cut bits (>=0, order-preserving) | 127-m tie-break.
            // Every real key (low field >= 32) > every pad key (low < 32).
            key[r] = ((unsigned long long)__float_as_uint(cut) << 32)
                   | (unsigned int)(127 - m);
        }
    } else {
        #pragma unroll
        for (int r = 0; r < 4; r++)
            key[r] = (unsigned int)(127 - (lane * 4 + r));
    }
    __syncwarp();

    // ---- 128-element bitonic sort, descending; element e = lane*4 + r ----
    #define CE_INTRA(A, Bq, UP) {                                            \
        unsigned long long x_ = key[A], y_ = key[Bq];                        \
        bool sw_ = (UP) ? (x_ < y_) : (x_ > y_);                             \
        if (sw_) { key[A] = y_; key[Bq] = x_; } }

    #define CE_SHFL(Mm, UP) {                                                \
        const bool keepmax_ = (UP) ^ ((lane & (Mm)) != 0);                   \
        _Pragma("unroll")                                                    \
        for (int r_ = 0; r_ < 4; r_++) {                                     \
            unsigned long long o_ = __shfl_xor_sync(0xffffffffu, key[r_], (Mm)); \
            bool take_ = keepmax_ ? (o_ > key[r_]) : (o_ < key[r_]);         \
            key[r_] = take_ ? o_ : key[r_];                                  \
        } }

    // k = 2 : j=1   (dir: pair(0,1) desc, pair(2,3) asc)
    CE_INTRA(0, 1, true)
    CE_INTRA(2, 3, false)
    // k = 4 : j=2,1
    { const bool up = ((lane & 1) == 0);
      CE_INTRA(0, 2, up) CE_INTRA(1, 3, up)
      CE_INTRA(0, 1, up) CE_INTRA(2, 3, up) }
    // k = 8 : j=4(shfl 1),2,1
    { const bool up = ((lane & 2) == 0);
      CE_SHFL(1, up)
      CE_INTRA(0, 2, up) CE_INTRA(1, 3, up)
      CE_INTRA(0, 1, up) CE_INTRA(2, 3, up) }
    // k = 16 : j=8(shfl 2),4(shfl 1),2,1
    { const bool up = ((lane & 4) == 0);
      CE_SHFL(2, up) CE_SHFL(1, up)
      CE_INTRA(0, 2, up) CE_INTRA(1, 3, up)
      CE_INTRA(0, 1, up) CE_INTRA(2, 3, up) }
    // k = 32
    { const bool up = ((lane & 8) == 0);
      CE_SHFL(4, up) CE_SHFL(2, up) CE_SHFL(1, up)
      CE_INTRA(0, 2, up) CE_INTRA(1, 3, up)
      CE_INTRA(0, 1, up) CE_INTRA(2, 3, up) }
    // k = 64
    { const bool up = ((lane & 16) == 0);
      CE_SHFL(8, up) CE_SHFL(4, up) CE_SHFL(2, up) CE_SHFL(1, up)
      CE_INTRA(0, 2, up) CE_INTRA(1, 3, up)
      CE_INTRA(0, 1, up) CE_INTRA(2, 3, up) }
    // k = 128 (final, all descending)
    { CE_SHFL(16, true) CE_SHFL(8, true) CE_SHFL(4, true) CE_SHFL(2, true) CE_SHFL(1, true)
      CE_INTRA(0, 2, true) CE_INTRA(1, 3, true)
      CE_INTRA(0, 1, true) CE_INTRA(2, 3, true) }

    __syncwarp();   // make cv writes visible across lanes before gather

    float* orow = out + (long)row * OUTW;
    if (lane < 24) {
        float v[12];
        #pragma unroll
        for (int r = 0; r < 4; r++) {
            const int om = 127 - (int)(key[r] & 127u);   // original m (0..95)
            v[r * 3 + 0] = cv[warp][om * 3 + 0];
            v[r * 3 + 1] = cv[warp][om * 3 + 1];
            v[r * 3 + 2] = cv[warp][om * 3 + 2];
        }
        float4* o4 = reinterpret_cast<float4*>(orow + lane * 12);
        o4[0] = make_float4(v[0], v[1], v[2],  v[3]);
        o4[1] = make_float4(v[4], v[5], v[6],  v[7]);
        o4[2] = make_float4(v[8], v[9], v[10], v[11]);
    } else {
        const float4 z = make_float4(0.f, 0.f, 0.f, 0.f);
        float4* o4 = reinterpret_cast<float4*>(orow + 288 + (lane - 24) * 12);
        o4[0] = z; o4[1] = z; o4[2] = z;
    }
}

extern "C" void kernel_launch(void* const* d_in, const int* in_sizes, int n_in,
                              void* d_out, int out_size) {
    const float* positions = (const float*)d_in[0];
    const float* cell      = (const float*)d_in[1];
    const float* offsets   = (const float*)d_in[2];
    const float* mask      = (const float*)d_in[3];
    const int*   neighbors = (const int*)d_in[4];
    float* out = (float*)d_out;

    deepmd_angular_kernel<<<(B_ * N_) / WARPS, 128>>>(positions, cell, offsets,
                                                      mask, neighbors, out);
}

// round 3
// speedup vs baseline: 3.1074x; 2.0082x over previous
#include <cuda_runtime.h>
#include <math.h>

#define B_ 8
#define N_ 4096
#define M_ 96
#define OUTW 384          // 3 * N_ANGULAR
#define RCUT 6.0f
#define WARPS 4

__global__ __launch_bounds__(128)
void deepmd_angular_kernel(const float* __restrict__ pos,
                           const float* __restrict__ cell,
                           const float* __restrict__ offs,
                           const float* __restrict__ mask,
                           const int*   __restrict__ neigh,
                           float* __restrict__ out) {
    const int warp = threadIdx.x >> 5;
    const int lane = threadIdx.x & 31;
    const int row  = blockIdx.x * WARPS + warp;   // b*N_ + n
    const int b    = row >> 12;                   // N_ = 4096

    __shared__ unsigned long long ckey[WARPS][M_];   // compacted keys
    __shared__ float              cvec[WARPS][M_][3];// compacted cut*dis_vec

    const float* cb = cell + b * 9;
    const float c00 = cb[0], c01 = cb[1], c02 = cb[2];
    const float c10 = cb[3], c11 = cb[4], c12 = cb[5];
    const float c20 = cb[6], c21 = cb[7], c22 = cb[8];

    const float* pi = pos + (long)row * 3;
    const float pix = pi[0], piy = pi[1], piz = pi[2];

    float cut4[4], vx4[4], vy4[4], vz4[4];

    if (lane < 24) {
        const long base = (long)row * M_ + lane * 4;
        const int4   jj = *reinterpret_cast<const int4*>(neigh + base);
        const float4 mm = *reinterpret_cast<const float4*>(mask + base);
        const float4* op = reinterpret_cast<const float4*>(offs + base * 3);
        const float4 oA = op[0], oB = op[1], oC = op[2];

        const float ox[4] = {oA.x, oA.w, oB.z, oC.y};
        const float oy[4] = {oA.y, oB.x, oB.w, oC.z};
        const float oz[4] = {oA.z, oB.y, oC.x, oC.w};
        const int   j4[4] = {jj.x, jj.y, jj.z, jj.w};
        const float m4[4] = {mm.x, mm.y, mm.z, mm.w};

        #pragma unroll
        for (int r = 0; r < 4; r++) {
            const float* pj = pos + ((long)b * N_ + j4[r]) * 3;
            const float dx = pj[0] - pix + ox[r] * c00 + oy[r] * c10 + oz[r] * c20;
            const float dy = pj[1] - piy + ox[r] * c01 + oy[r] * c11 + oz[r] * c21;
            const float dz = pj[2] - piz + ox[r] * c02 + oy[r] * c12 + oz[r] * c22;

            const float d = sqrtf(fmaf(dx, dx, fmaf(dy, dy, fmaf(dz, dz, 1e-12f))));

            float cut = 0.0f;
            if (m4[r] != 0.0f && d < RCUT)
                cut = 0.5f * (cospif(d * (1.0f / RCUT)) + 1.0f) / d;   // same as R2 (bit-stable ordering)

            cut4[r] = cut;
            vx4[r] = cut * dx; vy4[r] = cut * dy; vz4[r] = cut * dz;
        }
    } else {
        #pragma unroll
        for (int r = 0; r < 4; r++) cut4[r] = 0.0f;
    }

    // ---- warp compaction of nonzero-cut entries ----
    const unsigned lt = (1u << lane) - 1u;
    int K = 0;
    #pragma unroll
    for (int r = 0; r < 4; r++) {
        const bool nz = (cut4[r] > 0.0f);
        const unsigned bal = __ballot_sync(0xffffffffu, nz);
        if (nz) {
            const int pos_ = K + __popc(bal & lt);
            // key: cut bits (>=0, order-preserving) | compacted index.
            // Equal nonzero cuts only occur for identical (j,offset) pairs,
            // whose vectors are identical, so tie order is immaterial.
            ckey[warp][pos_] = ((unsigned long long)__float_as_uint(cut4[r]) << 32)
                             | (unsigned)pos_;
            cvec[warp][pos_][0] = vx4[r];
            cvec[warp][pos_][1] = vy4[r];
            cvec[warp][pos_][2] = vz4[r];
        }
        K += __popc(bal);
    }
    __syncwarp();

    float* orow = out + (long)row * OUTW;

    if (K <= 32) {
        // ---- fast path: 32-wide bitonic sort, descending (15 CEs) ----
        unsigned long long k0 = (lane < K) ? ckey[warp][lane] : 0ull;
        #pragma unroll
        for (int kk = 2; kk <= 32; kk <<= 1) {
            #pragma unroll
            for (int j = kk >> 1; j > 0; j >>= 1) {
                const bool keepmax = ((lane & kk) == 0) ^ ((lane & j) != 0);
                const unsigned long long o = __shfl_xor_sync(0xffffffffu, k0, j);
                const bool take = keepmax ? (o > k0) : (o < k0);
                k0 = take ? o : k0;
            }
        }
        // real entries: sorted position = lane
        if (lane < K) {
            const int c = (int)(k0 & 127u);
            const float vx = cvec[warp][c][0];
            const float vy = cvec[warp][c][1];
            const float vz = cvec[warp][c][2];
            orow[3 * lane + 0] = vx;
            orow[3 * lane + 1] = vy;
            orow[3 * lane + 2] = vz;
        }
        // zero-fill [3K, 384): scalar up to next float4 boundary, then float4s
        const int start = 3 * K;               // <= 96
        const int f0 = (start + 3) >> 2;       // first fully-zero float4
        if (lane == 0) {
            for (int i = start; i < 4 * f0; i++) orow[i] = 0.0f;
        }
        const float4 z = make_float4(0.f, 0.f, 0.f, 0.f);
        for (int f = f0 + lane; f < OUTW / 4; f += 32)
            reinterpret_cast<float4*>(orow)[f] = z;
    } else {
        // ---- fallback (K in 33..96, essentially never): 128-wide bitonic ----
        unsigned long long key[4];
        #pragma unroll
        for (int r = 0; r < 4; r++) {
            const int idx = lane * 4 + r;
            key[r] = (idx < K) ? ckey[warp][idx] : 0ull;
        }

        #define CE_INTRA(A, Bq, UP) {                                        \
            unsigned long long x_ = key[A], y_ = key[Bq];                    \
            bool sw_ = (UP) ? (x_ < y_) : (x_ > y_);                         \
            if (sw_) { key[A] = y_; key[Bq] = x_; } }

        #define CE_SHFL(Mm, UP) {                                            \
            const bool keepmax_ = (UP) ^ ((lane & (Mm)) != 0);               \
            _Pragma("unroll")                                                \
            for (int r_ = 0; r_ < 4; r_++) {                                 \
                unsigned long long o_ = __shfl_xor_sync(0xffffffffu, key[r_], (Mm)); \
                bool take_ = keepmax_ ? (o_ > key[r_]) : (o_ < key[r_]);     \
                key[r_] = take_ ? o_ : key[r_];                              \
            } }

        CE_INTRA(0, 1, true)
        CE_INTRA(2, 3, false)
        { const bool up = ((lane & 1) == 0);
          CE_INTRA(0, 2, up) CE_INTRA(1, 3, up)
          CE_INTRA(0, 1, up) CE_INTRA(2, 3, up) }
        { const bool up = ((lane & 2) == 0);
          CE_SHFL(1, up)
          CE_INTRA(0, 2, up) CE_INTRA(1, 3, up)
          CE_INTRA(0, 1, up) CE_INTRA(2, 3, up) }
        { const bool up = ((lane & 4) == 0);
          CE_SHFL(2, up) CE_SHFL(1, up)
          CE_INTRA(0, 2, up) CE_INTRA(1, 3, up)
          CE_INTRA(0, 1, up) CE_INTRA(2, 3, up) }
        { const bool up = ((lane & 8) == 0);
          CE_SHFL(4, up) CE_SHFL(2, up) CE_SHFL(1, up)
          CE_INTRA(0, 2, up) CE_INTRA(1, 3, up)
          CE_INTRA(0, 1, up) CE_INTRA(2, 3, up) }
        { const bool up = ((lane & 16) == 0);
          CE_SHFL(8, up) CE_SHFL(4, up) CE_SHFL(2, up) CE_SHFL(1, up)
          CE_INTRA(0, 2, up) CE_INTRA(1, 3, up)
          CE_INTRA(0, 1, up) CE_INTRA(2, 3, up) }
        { CE_SHFL(16, true) CE_SHFL(8, true) CE_SHFL(4, true) CE_SHFL(2, true) CE_SHFL(1, true)
          CE_INTRA(0, 2, true) CE_INTRA(1, 3, true)
          CE_INTRA(0, 1, true) CE_INTRA(2, 3, true) }

        if (lane < 24) {
            float v[12];
            #pragma unroll
            for (int r = 0; r < 4; r++) {
                const int p = lane * 4 + r;
                if (p < K) {
                    const int c = (int)(key[r] & 127u);
                    v[r * 3 + 0] = cvec[warp][c][0];
                    v[r * 3 + 1] = cvec[warp][c][1];
                    v[r * 3 + 2] = cvec[warp][c][2];
                } else {
                    v[r * 3 + 0] = 0.f; v[r * 3 + 1] = 0.f; v[r * 3 + 2] = 0.f;
                }
            }
            float4* o4 = reinterpret_cast<float4*>(orow + lane * 12);
            o4[0] = make_float4(v[0], v[1], v[2],  v[3]);
            o4[1] = make_float4(v[4], v[5], v[6],  v[7]);
            o4[2] = make_float4(v[8], v[9], v[10], v[11]);
        } else {
            const float4 z = make_float4(0.f, 0.f, 0.f, 0.f);
            float4* o4 = reinterpret_cast<float4*>(orow + 288 + (lane - 24) * 12);
            o4[0] = z; o4[1] = z; o4[2] = z;
        }
    }
}

extern "C" void kernel_launch(void* const* d_in, const int* in_sizes, int n_in,
                              void* d_out, int out_size) {
    const float* positions = (const float*)d_in[0];
    const float* cell      = (const float*)d_in[1];
    const float* offsets   = (const float*)d_in[2];
    const float* mask      = (const float*)d_in[3];
    const int*   neighbors = (const int*)d_in[4];
    float* out = (float*)d_out;

    deepmd_angular_kernel<<<(B_ * N_) / WARPS, 128>>>(positions, cell, offsets,
                                                      mask, neighbors, out);
}

// round 4
// speedup vs baseline: 3.2994x; 1.0618x over previous
#include <cuda_runtime.h>
#include <math.h>

#define B_ 8
#define N_ 4096
#define M_ 96
#define OUTW 384          // 3 * N_ANGULAR
#define RCUT 6.0f
#define WARPS 4

__global__ __launch_bounds__(128, 10)
void deepmd_angular_kernel(const float* __restrict__ pos,
                           const float* __restrict__ cell,
                           const float* __restrict__ offs,
                           const float* __restrict__ mask,
                           const int*   __restrict__ neigh,
                           float* __restrict__ out) {
    const int warp = threadIdx.x >> 5;
    const int lane = threadIdx.x & 31;
    const int row  = blockIdx.x * WARPS + warp;   // b*N_ + n
    const int b    = row >> 12;                   // N_ = 4096

    __shared__ unsigned long long ckey[WARPS][M_];    // compacted keys
    __shared__ float              cvec[WARPS][M_][3]; // compacted cut*dis_vec

    const float* cb = cell + b * 9;
    const float c00 = cb[0], c01 = cb[1], c02 = cb[2];
    const float c10 = cb[3], c11 = cb[4], c12 = cb[5];
    const float c20 = cb[6], c21 = cb[7], c22 = cb[8];

    const float* pi = pos + (long)row * 3;
    const float pix = pi[0], piy = pi[1], piz = pi[2];

    float cut4[4], vx4[4], vy4[4], vz4[4];

    if (lane < 24) {
        const long base = (long)row * M_ + lane * 4;
        const int4   jj = *reinterpret_cast<const int4*>(neigh + base);
        const float4 mm = *reinterpret_cast<const float4*>(mask + base);
        const float4* op = reinterpret_cast<const float4*>(offs + base * 3);
        const float4 oA = op[0], oB = op[1], oC = op[2];

        const float ox[4] = {oA.x, oA.w, oB.z, oC.y};
        const float oy[4] = {oA.y, oB.x, oB.w, oC.z};
        const float oz[4] = {oA.z, oB.y, oC.x, oC.w};
        const int   j4[4] = {jj.x, jj.y, jj.z, jj.w};
        const float m4[4] = {mm.x, mm.y, mm.z, mm.w};

        const float4* p4 = reinterpret_cast<const float4*>(pos);

        #pragma unroll
        for (int r = 0; r < 4; r++) {
            // gather position j as 1-2 LDG.128 instead of 3 scattered LDG.32
            const long gelem = (long)b * N_ + j4[r];
            const long byteo = gelem * 12;
            const long q     = byteo >> 4;         // aligned float4 index
            const int  rem   = (int)(byteo & 12);  // 0,4,8,12

            const float4 A = __ldg(p4 + q);
            float4 Bv = A;
            if (rem >= 8) Bv = __ldg(p4 + q + 1);  // predicated, in-bounds (total 16-aligned)

            const bool h8 = (rem & 8) != 0;
            const bool h4 = (rem & 4) != 0;
            const float px = h8 ? (h4 ? A.w  : A.z ) : (h4 ? A.y  : A.x);
            const float py = h8 ? (h4 ? Bv.x : A.w ) : (h4 ? A.z  : A.y);
            const float pz = h8 ? (h4 ? Bv.y : Bv.x) : (h4 ? A.w  : A.z);

            const float dx = px - pix + ox[r] * c00 + oy[r] * c10 + oz[r] * c20;
            const float dy = py - piy + ox[r] * c01 + oy[r] * c11 + oz[r] * c21;
            const float dz = pz - piz + ox[r] * c02 + oy[r] * c12 + oz[r] * c22;

            const float d = sqrtf(fmaf(dx, dx, fmaf(dy, dy, fmaf(dz, dz, 1e-12f))));

            float cut = 0.0f;
            if (m4[r] != 0.0f && d < RCUT)
                cut = 0.5f * (cospif(d * (1.0f / RCUT)) + 1.0f) / d;  // bit-stable vs R2/R3

            cut4[r] = cut;
            vx4[r] = cut * dx; vy4[r] = cut * dy; vz4[r] = cut * dz;
        }
    } else {
        #pragma unroll
        for (int r = 0; r < 4; r++) cut4[r] = 0.0f;
    }

    // ---- warp compaction of nonzero-cut entries ----
    const unsigned lt = (1u << lane) - 1u;
    int K = 0;
    #pragma unroll
    for (int r = 0; r < 4; r++) {
        const bool nz = (cut4[r] > 0.0f);
        const unsigned bal = __ballot_sync(0xffffffffu, nz);
        if (nz) {
            const int pos_ = K + __popc(bal & lt);
            // key: cut bits (>=0, order-preserving) | compacted index.
            // Equal nonzero cuts only occur for identical (j,offset) pairs,
            // whose vectors are identical, so tie order is immaterial.
            ckey[warp][pos_] = ((unsigned long long)__float_as_uint(cut4[r]) << 32)
                             | (unsigned)pos_;
            cvec[warp][pos_][0] = vx4[r];
            cvec[warp][pos_][1] = vy4[r];
            cvec[warp][pos_][2] = vz4[r];
        }
        K += __popc(bal);
    }
    __syncwarp();

    float* orow = out + (long)row * OUTW;

    if (K <= 32) {
        // ---- fast path: 32-wide bitonic sort, descending (15 CEs) ----
        unsigned long long k0 = (lane < K) ? ckey[warp][lane] : 0ull;
        #pragma unroll
        for (int kk = 2; kk <= 32; kk <<= 1) {
            #pragma unroll
            for (int j = kk >> 1; j > 0; j >>= 1) {
                const bool keepmax = ((lane & kk) == 0) ^ ((lane & j) != 0);
                const unsigned long long o = __shfl_xor_sync(0xffffffffu, k0, j);
                const bool take = keepmax ? (o > k0) : (o < k0);
                k0 = take ? o : k0;
            }
        }
        if (lane < K) {
            const int c = (int)(k0 & 127u);
            orow[3 * lane + 0] = cvec[warp][c][0];
            orow[3 * lane + 1] = cvec[warp][c][1];
            orow[3 * lane + 2] = cvec[warp][c][2];
        }
        // zero-fill [3K, 384)
        const int start = 3 * K;
        const int f0 = (start + 3) >> 2;
        if (lane == 0) {
            for (int i = start; i < 4 * f0; i++) orow[i] = 0.0f;
        }
        const float4 z = make_float4(0.f, 0.f, 0.f, 0.f);
        for (int f = f0 + lane; f < OUTW / 4; f += 32)
            reinterpret_cast<float4*>(orow)[f] = z;
    } else {
        // ---- fallback (K in 33..96, essentially never): 128-wide bitonic ----
        unsigned long long key[4];
        #pragma unroll
        for (int r = 0; r < 4; r++) {
            const int idx = lane * 4 + r;
            key[r] = (idx < K) ? ckey[warp][idx] : 0ull;
        }

        #define CE_INTRA(A, Bq, UP) {                                        \
            unsigned long long x_ = key[A], y_ = key[Bq];                    \
            bool sw_ = (UP) ? (x_ < y_) : (x_ > y_);                         \
            if (sw_) { key[A] = y_; key[Bq] = x_; } }

        #define CE_SHFL(Mm, UP) {                                            \
            const bool keepmax_ = (UP) ^ ((lane & (Mm)) != 0);               \
            _Pragma("unroll")                                                \
            for (int r_ = 0; r_ < 4; r_++) {                                 \
                unsigned long long o_ = __shfl_xor_sync(0xffffffffu, key[r_], (Mm)); \
                bool take_ = keepmax_ ? (o_ > key[r_]) : (o_ < key[r_]);     \
                key[r_] = take_ ? o_ : key[r_];                              \
            } }

        CE_INTRA(0, 1, true)
        CE_INTRA(2, 3, false)
        { const bool up = ((lane & 1) == 0);
          CE_INTRA(0, 2, up) CE_INTRA(1, 3, up)
          CE_INTRA(0, 1, up) CE_INTRA(2, 3, up) }
        { const bool up = ((lane & 2) == 0);
          CE_SHFL(1, up)
          CE_INTRA(0, 2, up) CE_INTRA(1, 3, up)
          CE_INTRA(0, 1, up) CE_INTRA(2, 3, up) }
        { const bool up = ((lane & 4) == 0);
          CE_SHFL(2, up) CE_SHFL(1, up)
          CE_INTRA(0, 2, up) CE_INTRA(1, 3, up)
          CE_INTRA(0, 1, up) CE_INTRA(2, 3, up) }
        { const bool up = ((lane & 8) == 0);
          CE_SHFL(4, up) CE_SHFL(2, up) CE_SHFL(1, up)
          CE_INTRA(0, 2, up) CE_INTRA(1, 3, up)
          CE_INTRA(0, 1, up) CE_INTRA(2, 3, up) }
        { const bool up = ((lane & 16) == 0);
          CE_SHFL(8, up) CE_SHFL(4, up) CE_SHFL(2, up) CE_SHFL(1, up)
          CE_INTRA(0, 2, up) CE_INTRA(1, 3, up)
          CE_INTRA(0, 1, up) CE_INTRA(2, 3, up) }
        { CE_SHFL(16, true) CE_SHFL(8, true) CE_SHFL(4, true) CE_SHFL(2, true) CE_SHFL(1, true)
          CE_INTRA(0, 2, true) CE_INTRA(1, 3, true)
          CE_INTRA(0, 1, true) CE_INTRA(2, 3, true) }

        if (lane < 24) {
            float v[12];
            #pragma unroll
            for (int r = 0; r < 4; r++) {
                const int p = lane * 4 + r;
                if (p < K) {
                    const int c = (int)(key[r] & 127u);
                    v[r * 3 + 0] = cvec[warp][c][0];
                    v[r * 3 + 1] = cvec[warp][c][1];
                    v[r * 3 + 2] = cvec[warp][c][2];
                } else {
                    v[r * 3 + 0] = 0.f; v[r * 3 + 1] = 0.f; v[r * 3 + 2] = 0.f;
                }
            }
            float4* o4 = reinterpret_cast<float4*>(orow + lane * 12);
            o4[0] = make_float4(v[0], v[1], v[2],  v[3]);
            o4[1] = make_float4(v[4], v[5], v[6],  v[7]);
            o4[2] = make_float4(v[8], v[9], v[10], v[11]);
        } else {
            const float4 z = make_float4(0.f, 0.f, 0.f, 0.f);
            float4* o4 = reinterpret_cast<float4*>(orow + 288 + (lane - 24) * 12);
            o4[0] = z; o4[1] = z; o4[2] = z;
        }
    }
}

extern "C" void kernel_launch(void* const* d_in, const int* in_sizes, int n_in,
                              void* d_out, int out_size) {
    const float* positions = (const float*)d_in[0];
    const float* cell      = (const float*)d_in[1];
    const float* offsets   = (const float*)d_in[2];
    const float* mask      = (const float*)d_in[3];
    const int*   neighbors = (const int*)d_in[4];
    float* out = (float*)d_out;

    deepmd_angular_kernel<<<(B_ * N_) / WARPS, 128>>>(positions, cell, offsets,
                                                      mask, neighbors, out);
}

// round 5
// speedup vs baseline: 3.4184x; 1.0361x over previous
#include <cuda_runtime.h>
#include <math.h>

#define B_ 8
#define N_ 4096
#define M_ 96
#define OUTW 384          // 3 * N_ANGULAR
#define RCUT 6.0f
#define WARPS 4

// ---- cold path: K in 33..96 (essentially never taken; isolated for regs) ----
__device__ __noinline__ void fallback_sort_output(
        const unsigned long long* __restrict__ ckey,
        const float (* __restrict__ cvec)[3],
        int K, int lane, float* __restrict__ orow) {
    unsigned long long key[4];
    #pragma unroll
    for (int r = 0; r < 4; r++) {
        const int idx = lane * 4 + r;
        key[r] = (idx < K) ? ckey[idx] : 0ull;
    }

    #define CE_INTRA(A, Bq, UP) {                                            \
        unsigned long long x_ = key[A], y_ = key[Bq];                        \
        bool sw_ = (UP) ? (x_ < y_) : (x_ > y_);                             \
        if (sw_) { key[A] = y_; key[Bq] = x_; } }

    #define CE_SHFL(Mm, UP) {                                                \
        const bool keepmax_ = (UP) ^ ((lane & (Mm)) != 0);                   \
        _Pragma("unroll")                                                    \
        for (int r_ = 0; r_ < 4; r_++) {                                     \
            unsigned long long o_ = __shfl_xor_sync(0xffffffffu, key[r_], (Mm)); \
            bool take_ = keepmax_ ? (o_ > key[r_]) : (o_ < key[r_]);         \
            key[r_] = take_ ? o_ : key[r_];                                  \
        } }

    CE_INTRA(0, 1, true)
    CE_INTRA(2, 3, false)
    { const bool up = ((lane & 1) == 0);
      CE_INTRA(0, 2, up) CE_INTRA(1, 3, up)
      CE_INTRA(0, 1, up) CE_INTRA(2, 3, up) }
    { const bool up = ((lane & 2) == 0);
      CE_SHFL(1, up)
      CE_INTRA(0, 2, up) CE_INTRA(1, 3, up)
      CE_INTRA(0, 1, up) CE_INTRA(2, 3, up) }
    { const bool up = ((lane & 4) == 0);
      CE_SHFL(2, up) CE_SHFL(1, up)
      CE_INTRA(0, 2, up) CE_INTRA(1, 3, up)
      CE_INTRA(0, 1, up) CE_INTRA(2, 3, up) }
    { const bool up = ((lane & 8) == 0);
      CE_SHFL(4, up) CE_SHFL(2, up) CE_SHFL(1, up)
      CE_INTRA(0, 2, up) CE_INTRA(1, 3, up)
      CE_INTRA(0, 1, up) CE_INTRA(2, 3, up) }
    { const bool up = ((lane & 16) == 0);
      CE_SHFL(8, up) CE_SHFL(4, up) CE_SHFL(2, up) CE_SHFL(1, up)
      CE_INTRA(0, 2, up) CE_INTRA(1, 3, up)
      CE_INTRA(0, 1, up) CE_INTRA(2, 3, up) }
    { CE_SHFL(16, true) CE_SHFL(8, true) CE_SHFL(4, true) CE_SHFL(2, true) CE_SHFL(1, true)
      CE_INTRA(0, 2, true) CE_INTRA(1, 3, true)
      CE_INTRA(0, 1, true) CE_INTRA(2, 3, true) }

    if (lane < 24) {
        float v[12];
        #pragma unroll
        for (int r = 0; r < 4; r++) {
            const int p = lane * 4 + r;
            if (p < K) {
                const int c = (int)(key[r] & 127u);
                v[r * 3 + 0] = cvec[c][0];
                v[r * 3 + 1] = cvec[c][1];
                v[r * 3 + 2] = cvec[c][2];
            } else {
                v[r * 3 + 0] = 0.f; v[r * 3 + 1] = 0.f; v[r * 3 + 2] = 0.f;
            }
        }
        float4* o4 = reinterpret_cast<float4*>(orow + lane * 12);
        o4[0] = make_float4(v[0], v[1], v[2],  v[3]);
        o4[1] = make_float4(v[4], v[5], v[6],  v[7]);
        o4[2] = make_float4(v[8], v[9], v[10], v[11]);
    } else {
        const float4 z = make_float4(0.f, 0.f, 0.f, 0.f);
        float4* o4 = reinterpret_cast<float4*>(orow + 288 + (lane - 24) * 12);
        o4[0] = z; o4[1] = z; o4[2] = z;
    }
}

__global__ __launch_bounds__(128, 12)
void deepmd_angular_kernel(const float* __restrict__ pos,
                           const float* __restrict__ cell,
                           const float* __restrict__ offs,
                           const float* __restrict__ mask,
                           const int*   __restrict__ neigh,
                           float* __restrict__ out) {
    const int warp = threadIdx.x >> 5;
    const int lane = threadIdx.x & 31;
    const int row  = blockIdx.x * WARPS + warp;   // b*N_ + n
    const int b    = row >> 12;                   // N_ = 4096

    __shared__ unsigned long long ckey[WARPS][M_];    // compacted keys
    __shared__ float              cvec[WARPS][M_][3]; // compacted cut*dis_vec

    const float* cb = cell + b * 9;
    const float c00 = cb[0], c01 = cb[1], c02 = cb[2];
    const float c10 = cb[3], c11 = cb[4], c12 = cb[5];
    const float c20 = cb[6], c21 = cb[7], c22 = cb[8];

    const float* pi = pos + (long)row * 3;
    const float pix = pi[0], piy = pi[1], piz = pi[2];

    // streaming loads (lanes 0..23 own 4 neighbors each)
    int4   jj = make_int4(0, 0, 0, 0);
    float4 mm = make_float4(0.f, 0.f, 0.f, 0.f);
    float4 oA = mm, oB = mm, oC = mm;
    if (lane < 24) {
        const long base = (long)row * M_ + lane * 4;
        jj = *reinterpret_cast<const int4*>(neigh + base);
        mm = *reinterpret_cast<const float4*>(mask + base);
        const float4* op = reinterpret_cast<const float4*>(offs + base * 3);
        oA = op[0]; oB = op[1]; oC = op[2];
    }

    const float4* p4 = reinterpret_cast<const float4*>(pos);
    const unsigned lt = (1u << lane) - 1u;
    int K = 0;

    #pragma unroll
    for (int r = 0; r < 4; r++) {
        float cut = 0.0f, vx = 0.0f, vy = 0.0f, vz = 0.0f;
        if (lane < 24) {
            const int   j   = (r == 0) ? jj.x : (r == 1) ? jj.y : (r == 2) ? jj.z : jj.w;
            const float msk = (r == 0) ? mm.x : (r == 1) ? mm.y : (r == 2) ? mm.z : mm.w;
            const float ox  = (r == 0) ? oA.x : (r == 1) ? oA.w : (r == 2) ? oB.z : oC.y;
            const float oy  = (r == 0) ? oA.y : (r == 1) ? oB.x : (r == 2) ? oB.w : oC.z;
            const float oz  = (r == 0) ? oA.z : (r == 1) ? oB.y : (r == 2) ? oC.x : oC.w;

            const long byteo = ((long)b * N_ + j) * 12;
            const long q     = byteo >> 4;
            const int  rem   = (int)(byteo & 12);

            const float4 A = __ldg(p4 + q);
            float4 Bv = A;
            if (rem >= 8) Bv = __ldg(p4 + q + 1);   // predicated; in-bounds

            const bool h8 = (rem & 8) != 0;
            const bool h4 = (rem & 4) != 0;
            const float px = h8 ? (h4 ? A.w  : A.z ) : (h4 ? A.y  : A.x);
            const float py = h8 ? (h4 ? Bv.x : A.w ) : (h4 ? A.z  : A.y);
            const float pz = h8 ? (h4 ? Bv.y : Bv.x) : (h4 ? A.w  : A.z);

            const float dx = px - pix + ox * c00 + oy * c10 + oz * c20;
            const float dy = py - piy + ox * c01 + oy * c11 + oz * c21;
            const float dz = pz - piz + ox * c02 + oy * c12 + oz * c22;

            const float d = sqrtf(fmaf(dx, dx, fmaf(dy, dy, fmaf(dz, dz, 1e-12f))));

            if (msk != 0.0f && d < RCUT)
                cut = 0.5f * (cospif(d * (1.0f / RCUT)) + 1.0f) / d;  // bit-identical to R2-R4

            vx = cut * dx; vy = cut * dy; vz = cut * dz;
        }

        // warp compaction of nonzero entries (all 32 lanes participate)
        const bool nz = (cut > 0.0f);
        const unsigned bal = __ballot_sync(0xffffffffu, nz);
        if (nz) {
            const int pos_ = K + __popc(bal & lt);
            // ties among nonzero cuts only occur for identical (j,offset)
            // pairs with identical vectors -> tie order immaterial.
            ckey[warp][pos_] = ((unsigned long long)__float_as_uint(cut) << 32)
                             | (unsigned)pos_;
            cvec[warp][pos_][0] = vx;
            cvec[warp][pos_][1] = vy;
            cvec[warp][pos_][2] = vz;
        }
        K += __popc(bal);
    }
    __syncwarp();

    float* orow = out + (long)row * OUTW;

    if (K <= 32) {
        unsigned long long k0 = (lane < K) ? ckey[warp][lane] : 0ull;

        #define CEW(J, UPX) {                                                \
            const bool keepmax = (UPX) ^ ((lane & (J)) != 0);                \
            const unsigned long long o = __shfl_xor_sync(0xffffffffu, k0, (J)); \
            const bool take = keepmax ? (o > k0) : (o < k0);                 \
            k0 = take ? o : k0; }

        if (K <= 16) {
            // 16-wide bitonic (10 CEs); lanes 16..31 sort zeros harmlessly
            { const bool up = ((lane & 2)  == 0); CEW(1, up) }
            { const bool up = ((lane & 4)  == 0); CEW(2, up) CEW(1, up) }
            { const bool up = ((lane & 8)  == 0); CEW(4, up) CEW(2, up) CEW(1, up) }
            { const bool up = ((lane & 16) == 0); CEW(8, up) CEW(4, up) CEW(2, up) CEW(1, up) }
        } else {
            // full 32-wide bitonic (15 CEs), descending
            { const bool up = ((lane & 2)  == 0); CEW(1, up) }
            { const bool up = ((lane & 4)  == 0); CEW(2, up) CEW(1, up) }
            { const bool up = ((lane & 8)  == 0); CEW(4, up) CEW(2, up) CEW(1, up) }
            { const bool up = ((lane & 16) == 0); CEW(8, up) CEW(4, up) CEW(2, up) CEW(1, up) }
            { CEW(16, true) CEW(8, true) CEW(4, true) CEW(2, true) CEW(1, true) }
        }

        if (lane < K) {
            const int c = (int)(k0 & 127u);
            orow[3 * lane + 0] = cvec[warp][c][0];
            orow[3 * lane + 1] = cvec[warp][c][1];
            orow[3 * lane + 2] = cvec[warp][c][2];
        }
        // zero-fill [3K, 384)
        const int start = 3 * K;
        const int f0 = (start + 3) >> 2;
        if (lane == 0) {
            for (int i = start; i < 4 * f0; i++) orow[i] = 0.0f;
        }
        const float4 z = make_float4(0.f, 0.f, 0.f, 0.f);
        for (int f = f0 + lane; f < OUTW / 4; f += 32)
            reinterpret_cast<float4*>(orow)[f] = z;
    } else {
        fallback_sort_output(&ckey[warp][0], &cvec[warp][0], K, lane, orow);
    }
}

extern "C" void kernel_launch(void* const* d_in, const int* in_sizes, int n_in,
                              void* d_out, int out_size) {
    const float* positions = (const float*)d_in[0];
    const float* cell      = (const float*)d_in[1];
    const float* offsets   = (const float*)d_in[2];
    const float* mask      = (const float*)d_in[3];
    const int*   neighbors = (const int*)d_in[4];
    float* out = (float*)d_out;

    deepmd_angular_kernel<<<(B_ * N_) / WARPS, 128>>>(positions, cell, offsets,
                                                      mask, neighbors, out);
}

// round 6
// speedup vs baseline: 3.4370x; 1.0054x over previous
#include <cuda_runtime.h>
#include <math.h>

#define B_ 8
#define N_ 4096
#define M_ 96
#define OUTW 384          // 3 * N_ANGULAR
#define RCUT 6.0f
#define WARPS 4

// ---- cold path: K in 33..96 (essentially never; correctness only) ----
__device__ __noinline__ void fallback_sort_output(
        const float4* __restrict__ svec,   // per-warp [M_]: (dx,dy,dz,d)
        unsigned long long* __restrict__ kbuf,  // per-warp [M_] scratch
        int K, int lane, float* __restrict__ orow) {
    unsigned long long key[4];
    #pragma unroll
    for (int r = 0; r < 4; r++) {
        const int idx = lane * 4 + r;
        if (idx < K) {
            const float4 s = svec[idx];
            const float cut = 0.5f * (cospif(s.w * (1.0f / RCUT)) + 1.0f) / s.w;
            key[r] = ((unsigned long long)__float_as_uint(cut) << 32) | (unsigned)idx;
        } else {
            key[r] = 0ull;
        }
    }

    #define CE_INTRA(A, Bq, UP) {                                            \
        unsigned long long x_ = key[A], y_ = key[Bq];                        \
        bool sw_ = (UP) ? (x_ < y_) : (x_ > y_);                             \
        if (sw_) { key[A] = y_; key[Bq] = x_; } }

    #define CE_SHFL(Mm, UP) {                                                \
        const bool keepmax_ = (UP) ^ ((lane & (Mm)) != 0);                   \
        _Pragma("unroll")                                                    \
        for (int r_ = 0; r_ < 4; r_++) {                                     \
            unsigned long long o_ = __shfl_xor_sync(0xffffffffu, key[r_], (Mm)); \
            bool take_ = keepmax_ ? (o_ > key[r_]) : (o_ < key[r_]);         \
            key[r_] = take_ ? o_ : key[r_];                                  \
        } }

    CE_INTRA(0, 1, true)
    CE_INTRA(2, 3, false)
    { const bool up = ((lane & 1) == 0);
      CE_INTRA(0, 2, up) CE_INTRA(1, 3, up)
      CE_INTRA(0, 1, up) CE_INTRA(2, 3, up) }
    { const bool up = ((lane & 2) == 0);
      CE_SHFL(1, up)
      CE_INTRA(0, 2, up) CE_INTRA(1, 3, up)
      CE_INTRA(0, 1, up) CE_INTRA(2, 3, up) }
    { const bool up = ((lane & 4) == 0);
      CE_SHFL(2, up) CE_SHFL(1, up)
      CE_INTRA(0, 2, up) CE_INTRA(1, 3, up)
      CE_INTRA(0, 1, up) CE_INTRA(2, 3, up) }
    { const bool up = ((lane & 8) == 0);
      CE_SHFL(4, up) CE_SHFL(2, up) CE_SHFL(1, up)
      CE_INTRA(0, 2, up) CE_INTRA(1, 3, up)
      CE_INTRA(0, 1, up) CE_INTRA(2, 3, up) }
    { const bool up = ((lane & 16) == 0);
      CE_SHFL(8, up) CE_SHFL(4, up) CE_SHFL(2, up) CE_SHFL(1, up)
      CE_INTRA(0, 2, up) CE_INTRA(1, 3, up)
      CE_INTRA(0, 1, up) CE_INTRA(2, 3, up) }
    { CE_SHFL(16, true) CE_SHFL(8, true) CE_SHFL(4, true) CE_SHFL(2, true) CE_SHFL(1, true)
      CE_INTRA(0, 2, true) CE_INTRA(1, 3, true)
      CE_INTRA(0, 1, true) CE_INTRA(2, 3, true) }
    (void)kbuf;

    if (lane < 24) {
        float v[12];
        #pragma unroll
        for (int r = 0; r < 4; r++) {
            const int p = lane * 4 + r;
            if (p < K) {
                const int c = (int)(key[r] & 127u);
                const float4 s = svec[c];
                const float cut = 0.5f * (cospif(s.w * (1.0f / RCUT)) + 1.0f) / s.w;
                v[r * 3 + 0] = cut * s.x;
                v[r * 3 + 1] = cut * s.y;
                v[r * 3 + 2] = cut * s.z;
            } else {
                v[r * 3 + 0] = 0.f; v[r * 3 + 1] = 0.f; v[r * 3 + 2] = 0.f;
            }
        }
        float4* o4 = reinterpret_cast<float4*>(orow + lane * 12);
        o4[0] = make_float4(v[0], v[1], v[2],  v[3]);
        o4[1] = make_float4(v[4], v[5], v[6],  v[7]);
        o4[2] = make_float4(v[8], v[9], v[10], v[11]);
    } else {
        const float4 z = make_float4(0.f, 0.f, 0.f, 0.f);
        float4* o4 = reinterpret_cast<float4*>(orow + 288 + (lane - 24) * 12);
        o4[0] = z; o4[1] = z; o4[2] = z;
    }
}

__global__ __launch_bounds__(128, 12)
void deepmd_angular_kernel(const float* __restrict__ pos,
                           const float* __restrict__ cell,
                           const float* __restrict__ offs,
                           const float* __restrict__ mask,
                           const int*   __restrict__ neigh,
                           float* __restrict__ out) {
    const int warp = threadIdx.x >> 5;
    const int lane = threadIdx.x & 31;
    const int row  = blockIdx.x * WARPS + warp;   // b*N_ + n
    const int b    = row >> 12;                   // N_ = 4096

    __shared__ float4 svec[WARPS][M_];                 // (dx,dy,dz,d) survivors
    __shared__ unsigned long long kbuf[WARPS][1];      // (unused scratch slot)

    const float* cb = cell + b * 9;
    const float c00 = cb[0], c01 = cb[1], c02 = cb[2];
    const float c10 = cb[3], c11 = cb[4], c12 = cb[5];
    const float c20 = cb[6], c21 = cb[7], c22 = cb[8];

    const float* pi = pos + (long)row * 3;
    const float pix = pi[0], piy = pi[1], piz = pi[2];

    int4   jj = make_int4(0, 0, 0, 0);
    float4 mm = make_float4(0.f, 0.f, 0.f, 0.f);
    float4 oA = mm, oB = mm, oC = mm;
    if (lane < 24) {
        const long base = (long)row * M_ + lane * 4;
        jj = *reinterpret_cast<const int4*>(neigh + base);
        mm = *reinterpret_cast<const float4*>(mask + base);
        const float4* op = reinterpret_cast<const float4*>(offs + base * 3);
        oA = op[0]; oB = op[1]; oC = op[2];
    }

    const float4* p4 = reinterpret_cast<const float4*>(pos);
    const unsigned lt = (1u << lane) - 1u;
    int K = 0;

    // ---- pass 1: displacement + distance only; compact survivors ----
    #pragma unroll
    for (int r = 0; r < 4; r++) {
        bool nz = false;
        float dx = 0.f, dy = 0.f, dz = 0.f, d = 0.f;
        if (lane < 24) {
            const int   j   = (r == 0) ? jj.x : (r == 1) ? jj.y : (r == 2) ? jj.z : jj.w;
            const float msk = (r == 0) ? mm.x : (r == 1) ? mm.y : (r == 2) ? mm.z : mm.w;
            const float ox  = (r == 0) ? oA.x : (r == 1) ? oA.w : (r == 2) ? oB.z : oC.y;
            const float oy  = (r == 0) ? oA.y : (r == 1) ? oB.x : (r == 2) ? oB.w : oC.z;
            const float oz  = (r == 0) ? oA.z : (r == 1) ? oB.y : (r == 2) ? oC.x : oC.w;

            const long byteo = ((long)b * N_ + j) * 12;
            const long q     = byteo >> 4;
            const int  rem   = (int)(byteo & 12);

            const float4 A = __ldg(p4 + q);
            float4 Bv = A;
            if (rem >= 8) Bv = __ldg(p4 + q + 1);   // predicated; in-bounds

            const bool h8 = (rem & 8) != 0;
            const bool h4 = (rem & 4) != 0;
            const float px = h8 ? (h4 ? A.w  : A.z ) : (h4 ? A.y  : A.x);
            const float py = h8 ? (h4 ? Bv.x : A.w ) : (h4 ? A.z  : A.y);
            const float pz = h8 ? (h4 ? Bv.y : Bv.x) : (h4 ? A.w  : A.z);

            dx = px - pix + ox * c00 + oy * c10 + oz * c20;
            dy = py - piy + ox * c01 + oy * c11 + oz * c21;
            dz = pz - piz + ox * c02 + oy * c12 + oz * c22;

            d = sqrtf(fmaf(dx, dx, fmaf(dy, dy, fmaf(dz, dz, 1e-12f))));

            // cut > 0  <=>  mask!=0 && d < RCUT (1+cos can't round to 0 here)
            nz = (msk != 0.0f) && (d < RCUT);
        }

        const unsigned bal = __ballot_sync(0xffffffffu, nz);
        if (nz) {
            const int pos_ = K + __popc(bal & lt);
            svec[warp][pos_] = make_float4(dx, dy, dz, d);
        }
        K += __popc(bal);
    }
    __syncwarp();

    float* orow = out + (long)row * OUTW;

    if (K <= 32) {
        // ---- pass 2: cut + key for survivors only (registers) ----
        float vx = 0.f, vy = 0.f, vz = 0.f;
        unsigned long long k0 = 0ull;
        if (lane < K) {
            const float4 s = svec[warp][lane];
            const float cut = 0.5f * (cospif(s.w * (1.0f / RCUT)) + 1.0f) / s.w; // bit-identical
            vx = cut * s.x; vy = cut * s.y; vz = cut * s.z;
            // ties among nonzero cuts => identical (j,offset) => identical
            // vectors, so tie order is immaterial.
            k0 = ((unsigned long long)__float_as_uint(cut) << 32) | (unsigned)lane;
        }

        #define CEW(J, UPX) {                                                \
            const bool keepmax = (UPX) ^ ((lane & (J)) != 0);                \
            const unsigned long long o = __shfl_xor_sync(0xffffffffu, k0, (J)); \
            const bool take = keepmax ? (o > k0) : (o < k0);                 \
            k0 = take ? o : k0; }

        if (K <= 16) {
            { const bool up = ((lane & 2)  == 0); CEW(1, up) }
            { const bool up = ((lane & 4)  == 0); CEW(2, up) CEW(1, up) }
            { const bool up = ((lane & 8)  == 0); CEW(4, up) CEW(2, up) CEW(1, up) }
            { const bool up = ((lane & 16) == 0); CEW(8, up) CEW(4, up) CEW(2, up) CEW(1, up) }
        } else {
            { const bool up = ((lane & 2)  == 0); CEW(1, up) }
            { const bool up = ((lane & 4)  == 0); CEW(2, up) CEW(1, up) }
            { const bool up = ((lane & 8)  == 0); CEW(4, up) CEW(2, up) CEW(1, up) }
            { const bool up = ((lane & 16) == 0); CEW(8, up) CEW(4, up) CEW(2, up) CEW(1, up) }
            { CEW(16, true) CEW(8, true) CEW(4, true) CEW(2, true) CEW(1, true) }
        }

        // gather sorted vectors via shuffle (source lane = compacted index)
        const int c = (int)(k0 & 63u);
        const float sx = __shfl_sync(0xffffffffu, vx, c);
        const float sy = __shfl_sync(0xffffffffu, vy, c);
        const float sz = __shfl_sync(0xffffffffu, vz, c);
        if (lane < K) {
            orow[3 * lane + 0] = sx;
            orow[3 * lane + 1] = sy;
            orow[3 * lane + 2] = sz;
        }
        // zero-fill [3K, 384)
        const int start = 3 * K;
        const int f0 = (start + 3) >> 2;
        if (lane == 0) {
            for (int i = start; i < 4 * f0; i++) orow[i] = 0.0f;
        }
        const float4 z = make_float4(0.f, 0.f, 0.f, 0.f);
        for (int f = f0 + lane; f < OUTW / 4; f += 32)
            reinterpret_cast<float4*>(orow)[f] = z;
    } else {
        fallback_sort_output(&svec[warp][0], &kbuf[warp][0], K, lane, orow);
    }
}

extern "C" void kernel_launch(void* const* d_in, const int* in_sizes, int n_in,
                              void* d_out, int out_size) {
    const float* positions = (const float*)d_in[0];
    const float* cell      = (const float*)d_in[1];
    const float* offsets   = (const float*)d_in[2];
    const float* mask      = (const float*)d_in[3];
    const int*   neighbors = (const int*)d_in[4];
    float* out = (float*)d_out;

    deepmd_angular_kernel<<<(B_ * N_) / WARPS, 128>>>(positions, cell, offsets,
                                                      mask, neighbors, out);
}